// round 7
// baseline (speedup 1.0000x reference)
#include <cuda_runtime.h>

#define CPG 42
#define IMG 192
#define CPG3 (CPG * CPG * CPG)
#define IMG2 ((size_t)IMG * IMG)
#define IMG3 (IMG2 * IMG)

template <bool GUARD>
__device__ __forceinline__ void ffd_tile(const float* __restrict__ v,
                                         float* __restrict__ out,
                                         int qy, int qz, int chBase) {
    __shared__ float s_W[5][4];          // B-spline weights per residue
    __shared__ float s_we[100];          // phase-C class table [5 cls][4 j][5 e]
    __shared__ float s_cp[4][16][CPG];   // control points [ch][(dz*4+dy)][cx]
    __shared__ float s_row[4][25][CPG];  // zy-collapsed   [ch][rz*5+ry][cx]

    const int tid = threadIdx.x;

    // ---- one-time weight tables ----
    if (tid < 20) {
        int r = tid >> 2, d = tid & 3;
        float u = (float)r * 0.2f;
        float w;
        if (d == 0)      { float a = 1.0f - u; w = a * a * a * (1.0f / 6.0f); }
        else if (d == 1) { w = (3.0f * u * u * u - 6.0f * u * u + 4.0f) * (1.0f / 6.0f); }
        else if (d == 2) { w = (((-3.0f * u + 3.0f) * u + 3.0f) * u + 1.0f) * (1.0f / 6.0f); }
        else             { w = u * u * u * (1.0f / 6.0f); }
        s_W[r][d] = w;
    } else if (tid < 40) {
        int tt = tid - 20;
        int c = tt >> 2, j = tt & 3;
        int xx = 4 * c + j;
        int qq = xx / 5;
        int rx = xx - qq * 5;
        int s = qq - ((4 * c) / 5);     // 0 or 1
        float u = (float)rx * 0.2f;
        float a = 1.0f - u;
        float w0 = a * a * a * (1.0f / 6.0f);
        float w1 = (3.0f * u * u * u - 6.0f * u * u + 4.0f) * (1.0f / 6.0f);
        float w2 = (((-3.0f * u + 3.0f) * u + 3.0f) * u + 1.0f) * (1.0f / 6.0f);
        float w3 = u * u * u * (1.0f / 6.0f);
        float* p = &s_we[(c * 4 + j) * 5];
        p[0] = s ? 0.0f : w0;
        p[1] = s ? w0 : w1;
        p[2] = s ? w1 : w2;
        p[3] = s ? w2 : w3;
        p[4] = s ? w3 : 0.0f;
    }

    // ---- Phase A: load 4 channel slabs as float2 (4*16*21 = 1344 pairs) ----
    const float* vcBase = v + (size_t)chBase * CPG3 +
                          ((size_t)qz * CPG + qy) * CPG;
    {
        #pragma unroll
        for (int k = 0; k < 6; k++) {           // 6*256 = 1536 >= 1344
            int i = tid + k * 256;
            if (i < 4 * 16 * 21) {
                int ch = i / (16 * 21);
                int rem = i - ch * (16 * 21);
                int r = rem / 21;
                int c2 = rem - r * 21;
                const float2 val = *reinterpret_cast<const float2*>(
                    vcBase + (size_t)ch * CPG3 +
                    ((size_t)(r >> 2) * CPG + (r & 3)) * CPG + 2 * c2);
                *reinterpret_cast<float2*>(&s_cp[ch][r][2 * c2]) = val;
            }
        }
    }
    __syncthreads();

    // ---- Phase B: fused z+y collapse. Task = (ch, cx): 168 scalar tasks. ----
    if (tid < 168) {
        const int ch = tid / CPG;
        const int cx = tid - ch * CPG;

        // 16 control points in registers, read once
        float cp[16];
        #pragma unroll
        for (int r = 0; r < 16; r++) cp[r] = s_cp[ch][r][cx];

        #pragma unroll
        for (int rz = 0; rz < 5; rz++) {
            const float wz0 = s_W[rz][0], wz1 = s_W[rz][1];
            const float wz2 = s_W[rz][2], wz3 = s_W[rz][3];
            float tz[4];
            #pragma unroll
            for (int dy = 0; dy < 4; dy++) {
                float acc =        wz0 * cp[0 + dy];
                acc = fmaf(wz1, cp[4 + dy], acc);
                acc = fmaf(wz2, cp[8 + dy], acc);
                acc = fmaf(wz3, cp[12 + dy], acc);
                tz[dy] = acc;
            }
            #pragma unroll
            for (int ry = 0; ry < 5; ry++) {
                float acc =        s_W[ry][0] * tz[0];
                acc = fmaf(s_W[ry][1], tz[1], acc);
                acc = fmaf(s_W[ry][2], tz[2], acc);
                acc = fmaf(s_W[ry][3], tz[3], acc);
                s_row[ch][rz * 5 + ry][cx] = acc;
            }
        }
    }
    __syncthreads();

    // ---- Phase C: x expansion ----
    if (tid < 240) {
        const int x4 = tid % 48;
        const int rz = tid / 48;
        const int x0 = x4 * 4;
        const int q  = x0 / 5;              // q+4 <= 41
        const int cls = x4 % 5;
        const int z  = qz * 5 + rz;
        const int y0 = qy * 5;
        const size_t zoff = (size_t)z * IMG2 + (size_t)y0 * IMG + (size_t)x0;

        float we[4][5];
        {
            const float* p = &s_we[cls * 20];
            #pragma unroll
            for (int j = 0; j < 4; j++)
                #pragma unroll
                for (int e = 0; e < 5; e++)
                    we[j][e] = p[j * 5 + e];
        }

        const bool zok = (!GUARD) || (z < IMG);
        #pragma unroll
        for (int ch = 0; ch < 4; ch++) {
            float* op = out + (size_t)(chBase + ch) * IMG3 + zoff;
            const float* rbase = &s_row[ch][rz * 5][q];
            #pragma unroll
            for (int ry = 0; ry < 5; ry++) {
                const float* rp = rbase + ry * CPG;
                float r0 = rp[0], r1 = rp[1], r2 = rp[2], r3 = rp[3], r4 = rp[4];
                float4 o;
                o.x = fmaf(we[0][0], r0, fmaf(we[0][1], r1, fmaf(we[0][2], r2,
                      fmaf(we[0][3], r3, we[0][4] * r4))));
                o.y = fmaf(we[1][0], r0, fmaf(we[1][1], r1, fmaf(we[1][2], r2,
                      fmaf(we[1][3], r3, we[1][4] * r4))));
                o.z = fmaf(we[2][0], r0, fmaf(we[2][1], r1, fmaf(we[2][2], r2,
                      fmaf(we[2][3], r3, we[2][4] * r4))));
                o.w = fmaf(we[3][0], r0, fmaf(we[3][1], r1, fmaf(we[3][2], r2,
                      fmaf(we[3][3], r3, we[3][4] * r4))));
                if (!GUARD || (zok && (y0 + ry < IMG)))
                    __stcs(reinterpret_cast<float4*>(op), o);
                op += IMG;
            }
        }
    }
}

// Interior: qy in [0,38), qz in [0,38). No guards, high occupancy target.
__global__ __launch_bounds__(256, 6) void ffd_interior(const float* __restrict__ v,
                                                       float* __restrict__ out) {
    ffd_tile<false>(v, out, blockIdx.x, blockIdx.y, blockIdx.z * 4);
}

// Boundary: qy==38 or qz==38. 77 tiles per channel-group.
__global__ __launch_bounds__(256) void ffd_boundary(const float* __restrict__ v,
                                                    float* __restrict__ out) {
    int t = blockIdx.x;
    int qy, qz;
    if (t < 39) { qy = t; qz = 38; }
    else        { qy = 38; qz = t - 39; }
    ffd_tile<true>(v, out, qy, qz, blockIdx.z * 4);
}

extern "C" void kernel_launch(void* const* d_in, const int* in_sizes, int n_in,
                              void* d_out, int out_size) {
    const float* v = (const float*)d_in[0];
    float* out = (float*)d_out;
    ffd_interior<<<dim3(38, 38, 3), 256>>>(v, out);
    ffd_boundary<<<dim3(77, 1, 3), 256>>>(v, out);
}

// round 8
// speedup vs baseline: 1.2384x; 1.2384x over previous
#include <cuda_runtime.h>

#define CPG 42
#define IMG 192
#define CPG3 (CPG * CPG * CPG)
#define IMG2 ((size_t)IMG * IMG)
#define IMG3 (IMG2 * IMG)

// Cubic B-spline weights at u = r/5, baked as compile-time constants.
__device__ static constexpr float BW[5][4] = {
    {0.1666666667f, 0.6666666667f, 0.1666666667f, 0.0000000000f},
    {0.0853333333f, 0.6306666667f, 0.2826666667f, 0.0013333333f},
    {0.0360000000f, 0.5386666667f, 0.4146666667f, 0.0106666667f},
    {0.0106666667f, 0.4146666667f, 0.5386666667f, 0.0360000000f},
    {0.0013333333f, 0.2826666667f, 0.6306666667f, 0.0853333333f},
};

__global__ __launch_bounds__(256) void ffd_kernel(const float* __restrict__ v,
                                                  float* __restrict__ out) {
    const int qy = blockIdx.x;          // 0..38
    const int qz = blockIdx.y;          // 0..38
    const int chBase = blockIdx.z * 4;  // 0,4,8

    __shared__ float s_we[100];          // phase-C class table [5 cls][4 j][5 e]
    __shared__ float s_row[4][25][CPG];  // zy-collapsed [ch][rz*5+ry][cx]

    const int tid = threadIdx.x;

    // ---- phase-C class weight table (20 threads) ----
    if (tid < 20) {
        int c = tid / 4, j = tid & 3;
        int xx = 4 * c + j;
        int qq = xx / 5;
        int rx = xx - qq * 5;
        int s = qq - ((4 * c) / 5);     // 0 or 1
        const float w0 = BW[rx][0], w1 = BW[rx][1];
        const float w2 = BW[rx][2], w3 = BW[rx][3];
        float* p = &s_we[(c * 4 + j) * 5];
        p[0] = s ? 0.0f : w0;
        p[1] = s ? w0 : w1;
        p[2] = s ? w1 : w2;
        p[3] = s ? w2 : w3;
        p[4] = s ? w3 : 0.0f;
    }

    // ---- Phase B: direct-LDG fused z+y collapse. Task = (ch, cx). ----
    if (tid < 168) {
        const int ch = tid / CPG;
        const int cx = tid - ch * CPG;
        const float* base = v + (size_t)(chBase + ch) * CPG3 +
                            ((size_t)qz * CPG + qy) * CPG + cx;

        // 16 control points straight from global (compile-time offsets, MLP=16)
        float cp[16];
        #pragma unroll
        for (int dz = 0; dz < 4; dz++)
            #pragma unroll
            for (int dy = 0; dy < 4; dy++)
                cp[dz * 4 + dy] = __ldg(base + (dz * CPG + dy) * CPG);

        #pragma unroll
        for (int rz = 0; rz < 5; rz++) {
            float tz[4];
            #pragma unroll
            for (int dy = 0; dy < 4; dy++) {
                float acc =        BW[rz][0] * cp[0 + dy];
                acc = fmaf(BW[rz][1], cp[4 + dy], acc);
                acc = fmaf(BW[rz][2], cp[8 + dy], acc);
                acc = fmaf(BW[rz][3], cp[12 + dy], acc);
                tz[dy] = acc;
            }
            #pragma unroll
            for (int ry = 0; ry < 5; ry++) {
                float acc =        BW[ry][0] * tz[0];
                acc = fmaf(BW[ry][1], tz[1], acc);
                acc = fmaf(BW[ry][2], tz[2], acc);
                acc = fmaf(BW[ry][3], tz[3], acc);
                s_row[ch][rz * 5 + ry][cx] = acc;
            }
        }
    }
    __syncthreads();   // orders s_we + s_row before phase C

    // ---- Phase C: x expansion ----
    if (tid < 240) {
        const int x4 = tid % 48;
        const int rz = tid / 48;
        const int x0 = x4 * 4;
        const int q  = x0 / 5;              // q+4 <= 41
        const int cls = x4 % 5;
        const int z  = qz * 5 + rz;
        const int y0 = qy * 5;
        const size_t zoff = (size_t)z * IMG2 + (size_t)y0 * IMG + (size_t)x0;

        float we[4][5];
        {
            const float* p = &s_we[cls * 20];
            #pragma unroll
            for (int j = 0; j < 4; j++)
                #pragma unroll
                for (int e = 0; e < 5; e++)
                    we[j][e] = p[j * 5 + e];
        }

        if (qy < 38 && qz < 38) {
            // ---- interior: no guards ----
            #pragma unroll
            for (int ch = 0; ch < 4; ch++) {
                float* op = out + (size_t)(chBase + ch) * IMG3 + zoff;
                const float* rbase = &s_row[ch][rz * 5][q];
                #pragma unroll
                for (int ry = 0; ry < 5; ry++) {
                    const float* rp = rbase + ry * CPG;
                    float r0 = rp[0], r1 = rp[1], r2 = rp[2], r3 = rp[3], r4 = rp[4];
                    float4 o;
                    o.x = fmaf(we[0][0], r0, fmaf(we[0][1], r1, fmaf(we[0][2], r2,
                          fmaf(we[0][3], r3, we[0][4] * r4))));
                    o.y = fmaf(we[1][0], r0, fmaf(we[1][1], r1, fmaf(we[1][2], r2,
                          fmaf(we[1][3], r3, we[1][4] * r4))));
                    o.z = fmaf(we[2][0], r0, fmaf(we[2][1], r1, fmaf(we[2][2], r2,
                          fmaf(we[2][3], r3, we[2][4] * r4))));
                    o.w = fmaf(we[3][0], r0, fmaf(we[3][1], r1, fmaf(we[3][2], r2,
                          fmaf(we[3][3], r3, we[3][4] * r4))));
                    __stcs(reinterpret_cast<float4*>(op), o);
                    op += IMG;
                }
            }
        } else {
            // ---- boundary: guarded ----
            const bool zok = (z < IMG);
            #pragma unroll
            for (int ch = 0; ch < 4; ch++) {
                float* op = out + (size_t)(chBase + ch) * IMG3 + zoff;
                const float* rbase = &s_row[ch][rz * 5][q];
                #pragma unroll
                for (int ry = 0; ry < 5; ry++) {
                    const float* rp = rbase + ry * CPG;
                    float r0 = rp[0], r1 = rp[1], r2 = rp[2], r3 = rp[3], r4 = rp[4];
                    float4 o;
                    o.x = fmaf(we[0][0], r0, fmaf(we[0][1], r1, fmaf(we[0][2], r2,
                          fmaf(we[0][3], r3, we[0][4] * r4))));
                    o.y = fmaf(we[1][0], r0, fmaf(we[1][1], r1, fmaf(we[1][2], r2,
                          fmaf(we[1][3], r3, we[1][4] * r4))));
                    o.z = fmaf(we[2][0], r0, fmaf(we[2][1], r1, fmaf(we[2][2], r2,
                          fmaf(we[2][3], r3, we[2][4] * r4))));
                    o.w = fmaf(we[3][0], r0, fmaf(we[3][1], r1, fmaf(we[3][2], r2,
                          fmaf(we[3][3], r3, we[3][4] * r4))));
                    if (zok && (y0 + ry < IMG))
                        __stcs(reinterpret_cast<float4*>(op), o);
                    op += IMG;
                }
            }
        }
    }
}

extern "C" void kernel_launch(void* const* d_in, const int* in_sizes, int n_in,
                              void* d_out, int out_size) {
    const float* v = (const float*)d_in[0];
    float* out = (float*)d_out;
    dim3 grid(39, 39, 3);   // (qy, qz, channel-group of 4)
    ffd_kernel<<<grid, 256>>>(v, out);
}